// round 5
// baseline (speedup 1.0000x reference)
#include <cuda_runtime.h>
#include <cstdint>

// Problem constants
#define B_   2
#define S_   4096
#define D_   1024
#define H_   16
#define DH_  64
#define DIL_ 4
#define L_   1024
#define R_   8192

// Scratch (device globals — no allocation allowed)
__device__ float g_q[(size_t)R_ * D_];
__device__ float g_k[(size_t)R_ * D_];
__device__ float g_v[(size_t)R_ * D_];
__device__ float g_ctx[(size_t)R_ * D_];
__device__ float g_atted[(size_t)R_ * D_];

// ---------------------------------------------------------------------------
// Helpers
// ---------------------------------------------------------------------------
__device__ __forceinline__ uint32_t f2tf32(float f) {
    uint32_t u;
    asm("cvt.rna.tf32.f32 %0, %1;" : "=r"(u) : "f"(f));
    return u;
}

__device__ __forceinline__ void mma_tf32(float c[4], const uint32_t a[4],
                                         const uint32_t b[2]) {
    asm volatile(
        "mma.sync.aligned.m16n8k8.row.col.f32.tf32.tf32.f32 "
        "{%0,%1,%2,%3}, {%4,%5,%6,%7}, {%8,%9}, {%0,%1,%2,%3};"
        : "+f"(c[0]), "+f"(c[1]), "+f"(c[2]), "+f"(c[3])
        : "r"(a[0]), "r"(a[1]), "r"(a[2]), "r"(a[3]), "r"(b[0]), "r"(b[1]));
}

__device__ __forceinline__ uint32_t smem_u32(const void* p) {
    uint32_t a;
    asm("{ .reg .u64 t; cvta.to.shared.u64 t, %1; cvt.u32.u64 %0, t; }"
        : "=r"(a) : "l"(p));
    return a;
}

__device__ __forceinline__ void cp16(uint32_t saddr, const void* gptr) {
    asm volatile("cp.async.ca.shared.global [%0], [%1], 16;"
                 :: "r"(saddr), "l"(gptr));
}
#define CP_COMMIT() asm volatile("cp.async.commit_group;" ::: "memory")
#define CP_WAIT(n)  asm volatile("cp.async.wait_group %0;" :: "n"(n) : "memory")

// ---------------------------------------------------------------------------
// tf32 warp-MMA GEMM with register-prefetch pipelining.
// C[r,o] = sum_i A'[r,i]*W[o,i] + b[o]; 128x128 CTA tile, BK=32, 8 warps.
// round_out=1: outputs rounded to tf32 (q,k,v for MMA attention consumption).
// ---------------------------------------------------------------------------
#define LDPAD 36

__global__ void __launch_bounds__(256) gemm_mma(
    const float* __restrict__ x,
    const float* __restrict__ Wq, const float* __restrict__ bq,
    const float* __restrict__ Wk, const float* __restrict__ bk,
    const float* __restrict__ Wv, const float* __restrict__ bv,
    float* __restrict__ out_override, int mode, int round_out)
{
    __shared__ uint32_t As[128 * LDPAD];
    __shared__ uint32_t Bs[128 * LDPAD];

    const int tid  = threadIdx.x;
    const int wid  = tid >> 5;
    const int lane = tid & 31;
    const int lr   = lane >> 2;
    const int lc   = lane & 3;
    const int wm0  = (wid >> 2) * 64;
    const int wn0  = (wid & 3) * 32;

    const float* W; const float* bias; float* out; const float* A;
    if (mode == 0) {
        A = x;
        if (blockIdx.z == 0)      { W = Wq; bias = bq; out = g_q; }
        else if (blockIdx.z == 1) { W = Wk; bias = bk; out = g_k; }
        else                      { W = Wv; bias = bv; out = g_v; }
    } else {
        A = g_ctx; W = Wq; bias = bq; out = out_override;
    }

    const int rm0 = blockIdx.y * 128;
    const int on0 = blockIdx.x * 128;

    const int ldrow = tid >> 3;
    const int ldc4  = (tid & 7) * 4;
    const float* arow[4];
    const float* brow[4];
    #pragma unroll
    for (int p = 0; p < 4; p++) {
        int r = rm0 + p * 32 + ldrow;
        int src;
        if (mode == 0) {
            int bb = r >> 10, l = r & 1023;
            src = ((bb >> 2) << 12) + (l << 2) + (bb & 3);
        } else {
            int b = r >> 12, s = r & 4095;
            src = ((b << 2) + (s & 3)) * L_ + (s >> 2);
        }
        arow[p] = A + (size_t)src * D_ + ldc4;
        brow[p] = W + (size_t)(on0 + p * 32 + ldrow) * D_ + ldc4;
    }

    float acc[4][4][4] = {};
    float4 pa[4], pb[4];   // register prefetch buffers

    #pragma unroll
    for (int p = 0; p < 4; p++) {
        pa[p] = *(const float4*)(arow[p]);
        pb[p] = *(const float4*)(brow[p]);
    }

    for (int c = 0; c < 32; c++) {
        // store prefetched chunk (with rna tf32 rounding)
        #pragma unroll
        for (int p = 0; p < 4; p++) {
            uint4 au = make_uint4(f2tf32(pa[p].x), f2tf32(pa[p].y),
                                  f2tf32(pa[p].z), f2tf32(pa[p].w));
            uint4 bu = make_uint4(f2tf32(pb[p].x), f2tf32(pb[p].y),
                                  f2tf32(pb[p].z), f2tf32(pb[p].w));
            *(uint4*)&As[(p * 32 + ldrow) * LDPAD + ldc4] = au;
            *(uint4*)&Bs[(p * 32 + ldrow) * LDPAD + ldc4] = bu;
        }
        __syncthreads();

        // issue next chunk's loads (latency hidden behind MMAs below)
        if (c < 31) {
            const int k1 = (c + 1) * 32;
            #pragma unroll
            for (int p = 0; p < 4; p++) {
                pa[p] = *(const float4*)(arow[p] + k1);
                pb[p] = *(const float4*)(brow[p] + k1);
            }
        }

        #pragma unroll
        for (int kk = 0; kk < 4; kk++) {
            const int kb = kk * 8;
            uint32_t a[4][4], b[4][2];
            #pragma unroll
            for (int mf = 0; mf < 4; mf++) {
                const int r0 = (wm0 + mf * 16 + lr) * LDPAD + kb + lc;
                a[mf][0] = As[r0];
                a[mf][1] = As[r0 + 8 * LDPAD];
                a[mf][2] = As[r0 + 4];
                a[mf][3] = As[r0 + 8 * LDPAD + 4];
            }
            #pragma unroll
            for (int nf = 0; nf < 4; nf++) {
                const int r0 = (wn0 + nf * 8 + lr) * LDPAD + kb + lc;
                b[nf][0] = Bs[r0];
                b[nf][1] = Bs[r0 + 4];
            }
            #pragma unroll
            for (int mf = 0; mf < 4; mf++)
                #pragma unroll
                for (int nf = 0; nf < 4; nf++)
                    mma_tf32(acc[mf][nf], a[mf], b[nf]);
        }
        __syncthreads();
    }

    #pragma unroll
    for (int mf = 0; mf < 4; mf++) {
        const int row0 = rm0 + wm0 + mf * 16 + lr;
        #pragma unroll
        for (int nf = 0; nf < 4; nf++) {
            const int col = on0 + wn0 + nf * 8 + 2 * lc;
            const float bx = bias[col], by = bias[col + 1];
            float o00 = acc[mf][nf][0] + bx, o01 = acc[mf][nf][1] + by;
            float o10 = acc[mf][nf][2] + bx, o11 = acc[mf][nf][3] + by;
            if (round_out) {
                o00 = __uint_as_float(f2tf32(o00));
                o01 = __uint_as_float(f2tf32(o01));
                o10 = __uint_as_float(f2tf32(o10));
                o11 = __uint_as_float(f2tf32(o11));
            }
            *(float2*)(out + (size_t)row0 * D_ + col) = make_float2(o00, o01);
            *(float2*)(out + (size_t)(row0 + 8) * D_ + col) = make_float2(o10, o11);
        }
    }
}

// ---------------------------------------------------------------------------
// Attention via tf32 warp MMA + cp.async double-buffered K/V staging.
// q,k,v are tf32-exact fp32 (rounded in GEMM epilogue) -> raw copies feed MMA
// with no conversion error. Q scale (1/8) applied to S post-MMA.
// Dynamic smem: Ks[2][64*APAD] | Vs[2][64*APAD]  (69,632 B).
// ---------------------------------------------------------------------------
#define APAD 68
#define KTW  (64 * APAD)

__global__ void __launch_bounds__(128) attn_mma()
{
    extern __shared__ uint32_t dsm[];
    const uint32_t sb = smem_u32(dsm);

    const int tid  = threadIdx.x;
    const int wid  = tid >> 5;
    const int lane = tid & 31;
    const int lr   = lane >> 2;
    const int lc   = lane & 3;
    const int bbh  = blockIdx.y;
    const int bb   = bbh >> 4;
    const int h    = bbh & 15;
    const int q0   = blockIdx.x * 64;

    const int srow = tid >> 1;
    const int scol = (tid & 1) * 32;

    const float* qg = g_q + (size_t)(bb * L_ + q0 + srow) * D_ + h * DH_ + scol;
    const float* kg = g_k + (size_t)(bb * L_) * D_ + h * DH_;
    const float* vg = g_v + (size_t)(bb * L_) * D_ + h * DH_;

    const uint32_t stg = (uint32_t)(srow * APAD + scol) * 4u;

    // group 0: Q -> Ks[1] staging
    #pragma unroll
    for (int j = 0; j < 8; j++)
        cp16(sb + KTW * 4 + stg + j * 16, qg + j * 4);
    CP_COMMIT();
    // group 1: K0,V0 -> buffer 0
    #pragma unroll
    for (int j = 0; j < 8; j++) {
        cp16(sb + stg + j * 16, kg + (size_t)srow * D_ + scol + j * 4);
        cp16(sb + 2 * KTW * 4 + stg + j * 16, vg + (size_t)srow * D_ + scol + j * 4);
    }
    CP_COMMIT();

    CP_WAIT(1);
    __syncthreads();

    // Q fragments from Ks[1]
    uint32_t qa[8][4];
    #pragma unroll
    for (int kk = 0; kk < 8; kk++) {
        const int r0 = KTW + (wid * 16 + lr) * APAD + kk * 8 + lc;
        qa[kk][0] = dsm[r0];
        qa[kk][1] = dsm[r0 + 8 * APAD];
        qa[kk][2] = dsm[r0 + 4];
        qa[kk][3] = dsm[r0 + 8 * APAD + 4];
    }

    float O[8][4] = {};
    float m0 = -1e30f, m1 = -1e30f, l0 = 0.f, l1 = 0.f;

    for (int kt = 0; kt < 16; kt++) {
        const int buf = kt & 1;
        uint32_t* Ks = dsm + buf * KTW;
        uint32_t* Vs = dsm + (2 + buf) * KTW;

        CP_WAIT(0);          // tile kt arrived
        __syncthreads();     // visible to all; prior compute done everywhere

        if (kt < 15) {       // prefetch tile kt+1 into other buffer
            const uint32_t ob = (uint32_t)(buf ^ 1) * KTW * 4;
            const float* kp = kg + (size_t)((kt + 1) * 64 + srow) * D_ + scol;
            const float* vp = vg + (size_t)((kt + 1) * 64 + srow) * D_ + scol;
            #pragma unroll
            for (int j = 0; j < 8; j++) {
                cp16(sb + ob + stg + j * 16, kp + j * 4);
                cp16(sb + 2 * KTW * 4 + ob + stg + j * 16, vp + j * 4);
            }
            CP_COMMIT();
        }

        // --- S = Q @ K^T (16x64 per warp) ---
        float s[8][4] = {};
        #pragma unroll
        for (int kk = 0; kk < 8; kk++) {
            uint32_t b[8][2];
            #pragma unroll
            for (int nf = 0; nf < 8; nf++) {
                const int r0 = (nf * 8 + lr) * APAD + kk * 8 + lc;
                b[nf][0] = Ks[r0];
                b[nf][1] = Ks[r0 + 4];
            }
            #pragma unroll
            for (int nf = 0; nf < 8; nf++)
                mma_tf32(s[nf], qa[kk], b[nf]);
        }
        __syncthreads();   // all warps done reading Ks -> reuse as P

        // --- scale + online softmax (rows lr, lr+8) ---
        float ml0 = -1e30f, ml1 = -1e30f;
        #pragma unroll
        for (int nf = 0; nf < 8; nf++) {
            s[nf][0] *= 0.125f; s[nf][1] *= 0.125f;
            s[nf][2] *= 0.125f; s[nf][3] *= 0.125f;
            ml0 = fmaxf(ml0, fmaxf(s[nf][0], s[nf][1]));
            ml1 = fmaxf(ml1, fmaxf(s[nf][2], s[nf][3]));
        }
        ml0 = fmaxf(ml0, __shfl_xor_sync(0xffffffffu, ml0, 1));
        ml0 = fmaxf(ml0, __shfl_xor_sync(0xffffffffu, ml0, 2));
        ml1 = fmaxf(ml1, __shfl_xor_sync(0xffffffffu, ml1, 1));
        ml1 = fmaxf(ml1, __shfl_xor_sync(0xffffffffu, ml1, 2));
        const float mn0 = fmaxf(m0, ml0), mn1 = fmaxf(m1, ml1);
        const float c0 = __expf(m0 - mn0), c1 = __expf(m1 - mn1);
        float rs0 = 0.f, rs1 = 0.f;
        #pragma unroll
        for (int nf = 0; nf < 8; nf++) {
            s[nf][0] = __expf(s[nf][0] - mn0);
            s[nf][1] = __expf(s[nf][1] - mn0);
            s[nf][2] = __expf(s[nf][2] - mn1);
            s[nf][3] = __expf(s[nf][3] - mn1);
            rs0 += s[nf][0] + s[nf][1];
            rs1 += s[nf][2] + s[nf][3];
        }
        rs0 += __shfl_xor_sync(0xffffffffu, rs0, 1);
        rs0 += __shfl_xor_sync(0xffffffffu, rs0, 2);
        rs1 += __shfl_xor_sync(0xffffffffu, rs1, 1);
        rs1 += __shfl_xor_sync(0xffffffffu, rs1, 2);
        l0 = l0 * c0 + rs0;  m0 = mn0;
        l1 = l1 * c1 + rs1;  m1 = mn1;
        #pragma unroll
        for (int nf = 0; nf < 8; nf++) {
            O[nf][0] *= c0; O[nf][1] *= c0;
            O[nf][2] *= c1; O[nf][3] *= c1;
        }

        // --- P -> SMEM (warp-private rows, rna-rounded) ---
        #pragma unroll
        for (int nf = 0; nf < 8; nf++) {
            const int p0 = (wid * 16 + lr) * APAD + nf * 8 + 2 * lc;
            Ks[p0]                = f2tf32(s[nf][0]);
            Ks[p0 + 1]            = f2tf32(s[nf][1]);
            Ks[p0 + 8 * APAD]     = f2tf32(s[nf][2]);
            Ks[p0 + 8 * APAD + 1] = f2tf32(s[nf][3]);
        }
        __syncwarp();

        // --- O += P @ V ---
        #pragma unroll
        for (int kk = 0; kk < 8; kk++) {
            uint32_t a[4];
            const int r0 = (wid * 16 + lr) * APAD + kk * 8 + lc;
            a[0] = Ks[r0];
            a[1] = Ks[r0 + 8 * APAD];
            a[2] = Ks[r0 + 4];
            a[3] = Ks[r0 + 8 * APAD + 4];
            uint32_t b[8][2];
            #pragma unroll
            for (int nf = 0; nf < 8; nf++) {
                b[nf][0] = Vs[(kk * 8 + lc) * APAD + nf * 8 + lr];
                b[nf][1] = Vs[(kk * 8 + lc + 4) * APAD + nf * 8 + lr];
            }
            #pragma unroll
            for (int nf = 0; nf < 8; nf++)
                mma_tf32(O[nf], a, b[nf]);
        }
        __syncthreads();   // all P/V reads done before next-iter overwrite
    }

    const float inv0 = 1.f / l0, inv1 = 1.f / l1;
    float* og = g_ctx + (size_t)(bb * L_ + q0 + wid * 16) * D_ + h * DH_;
    #pragma unroll
    for (int nf = 0; nf < 8; nf++) {
        const int col = nf * 8 + 2 * lc;
        *(float2*)(og + (size_t)lr * D_ + col) =
            make_float2(O[nf][0] * inv0, O[nf][1] * inv0);
        *(float2*)(og + (size_t)(lr + 8) * D_ + col) =
            make_float2(O[nf][2] * inv1, O[nf][3] * inv1);
    }
}

// ---------------------------------------------------------------------------
// final = LayerNorm(atted + x) * gamma + beta.
// ---------------------------------------------------------------------------
__global__ void __launch_bounds__(256) ln_kernel(
    const float* __restrict__ x,
    const float* __restrict__ atted_ext,
    const float* __restrict__ gamma, const float* __restrict__ beta,
    float* __restrict__ final_out)
{
    const float* atted = atted_ext;
    const int r = blockIdx.x;
    const float* xa = x     + (size_t)r * D_;
    const float* aa = atted + (size_t)r * D_;
    const int tid = threadIdx.x;

    float v[4];
    float s1 = 0.f, s2 = 0.f;
    #pragma unroll
    for (int i = 0; i < 4; i++) {
        int c = tid + i * 256;
        float val = xa[c] + aa[c];
        v[i] = val;
        s1 += val; s2 += val * val;
    }
    #pragma unroll
    for (int off = 16; off; off >>= 1) {
        s1 += __shfl_xor_sync(0xffffffffu, s1, off);
        s2 += __shfl_xor_sync(0xffffffffu, s2, off);
    }
    __shared__ float red[16];
    int warp = tid >> 5, lane = tid & 31;
    if (lane == 0) { red[warp] = s1; red[8 + warp] = s2; }
    __syncthreads();
    float t1 = 0.f, t2 = 0.f;
    #pragma unroll
    for (int w = 0; w < 8; w++) { t1 += red[w]; t2 += red[8 + w]; }
    float mu  = t1 * (1.f / 1024.f);
    float var = t2 * (1.f / 1024.f) - mu * mu;
    float rstd = rsqrtf(var + 1e-5f);
    #pragma unroll
    for (int i = 0; i < 4; i++) {
        int c = tid + i * 256;
        final_out[(size_t)r * D_ + c] = (v[i] - mu) * rstd * gamma[c] + beta[c];
    }
}

// ---------------------------------------------------------------------------
extern "C" void kernel_launch(void* const* d_in, const int* in_sizes, int n_in,
                              void* d_out, int out_size)
{
    (void)in_sizes; (void)n_in;
    const float* x     = (const float*)d_in[0];
    const float* Wq    = (const float*)d_in[1];
    const float* bq    = (const float*)d_in[2];
    const float* Wk    = (const float*)d_in[3];
    const float* bk    = (const float*)d_in[4];
    const float* Wv    = (const float*)d_in[5];
    const float* bv    = (const float*)d_in[6];
    const float* Wf    = (const float*)d_in[7];
    const float* bf    = (const float*)d_in[8];
    const float* gamma = (const float*)d_in[9];
    const float* beta  = (const float*)d_in[10];
    float* out = (float*)d_out;

    const long long both = 2LL * R_ * D_;
    float* atted = (out_size >= both) ? (out + (size_t)R_ * D_) : nullptr;
    if (!atted) {
        static float* h_atted_ptr = nullptr;
        if (!h_atted_ptr) cudaGetSymbolAddress((void**)&h_atted_ptr, g_atted);
        atted = h_atted_ptr;
    }

    static bool attr_set = false;
    if (!attr_set) {
        cudaFuncSetAttribute(attn_mma,
                             cudaFuncAttributeMaxDynamicSharedMemorySize,
                             4 * KTW * 4);
        attr_set = true;
    }

    // QKV projections (outputs tf32-rounded for the attention MMAs)
    gemm_mma<<<dim3(D_/128, R_/128, 3), 256>>>(
        x, Wq, bq, Wk, bk, Wv, bv, nullptr, 0, 1);
    // Attention (tf32 warp MMA flash, cp.async pipelined)
    attn_mma<<<dim3(L_/64, B_ * DIL_ * H_), 128, 4 * KTW * 4>>>();
    // Output projection (unrounded fp32 output)
    gemm_mma<<<dim3(D_/128, R_/128, 1), 256>>>(
        x, Wf, bf, nullptr, nullptr, nullptr, nullptr, atted, 1, 0);
    ln_kernel<<<R_, 256>>>(x, atted, gamma, beta, out);
}

// round 6
// speedup vs baseline: 1.0946x; 1.0946x over previous
#include <cuda_runtime.h>
#include <cstdint>

// Problem constants
#define B_   2
#define S_   4096
#define D_   1024
#define H_   16
#define DH_  64
#define DIL_ 4
#define L_   1024
#define R_   8192

// Scratch (device globals — no allocation allowed)
__device__ float g_q[(size_t)R_ * D_];
__device__ float g_k[(size_t)R_ * D_];
__device__ float g_v[(size_t)R_ * D_];
__device__ float g_ctx[(size_t)R_ * D_];
__device__ float g_atted[(size_t)R_ * D_];
__device__ float g_xr[(size_t)R_ * D_];        // tf32-rounded, xr-permuted x
__device__ float g_w[4][(size_t)D_ * D_];      // tf32-rounded Wq,Wk,Wv,Wf

// ---------------------------------------------------------------------------
// Helpers
// ---------------------------------------------------------------------------
__device__ __forceinline__ uint32_t f2tf32(float f) {
    uint32_t u;
    asm("cvt.rna.tf32.f32 %0, %1;" : "=r"(u) : "f"(f));
    return u;
}
__device__ __forceinline__ float rndtf32(float f) {
    return __uint_as_float(f2tf32(f));
}

__device__ __forceinline__ void mma_tf32(float c[4], const uint32_t a[4],
                                         const uint32_t b[2]) {
    asm volatile(
        "mma.sync.aligned.m16n8k8.row.col.f32.tf32.tf32.f32 "
        "{%0,%1,%2,%3}, {%4,%5,%6,%7}, {%8,%9}, {%0,%1,%2,%3};"
        : "+f"(c[0]), "+f"(c[1]), "+f"(c[2]), "+f"(c[3])
        : "r"(a[0]), "r"(a[1]), "r"(a[2]), "r"(a[3]), "r"(b[0]), "r"(b[1]));
}

__device__ __forceinline__ uint32_t smem_u32(const void* p) {
    uint32_t a;
    asm("{ .reg .u64 t; cvta.to.shared.u64 t, %1; cvt.u32.u64 %0, t; }"
        : "=r"(a) : "l"(p));
    return a;
}

__device__ __forceinline__ void cp16(uint32_t saddr, const void* gptr) {
    asm volatile("cp.async.ca.shared.global [%0], [%1], 16;"
                 :: "r"(saddr), "l"(gptr));
}
#define CP_COMMIT() asm volatile("cp.async.commit_group;" ::: "memory")
#define CP_WAIT(n)  asm volatile("cp.async.wait_group %0;" :: "n"(n) : "memory")

// ---------------------------------------------------------------------------
// Prep: round + permute x into g_xr; round W's into g_w.
// ---------------------------------------------------------------------------
__global__ void __launch_bounds__(256) prep_x(const float* __restrict__ x)
{
    const int idx = blockIdx.x * 256 + threadIdx.x;   // one float4 each
    const int r  = idx >> 8;
    const int c4 = (idx & 255) * 4;
    const int bb = r >> 10, l = r & 1023;
    const int src = ((bb >> 2) << 12) + (l << 2) + (bb & 3);
    float4 v = *(const float4*)(x + (size_t)src * D_ + c4);
    float4 o = make_float4(rndtf32(v.x), rndtf32(v.y), rndtf32(v.z), rndtf32(v.w));
    *(float4*)(g_xr + (size_t)r * D_ + c4) = o;
}

__global__ void __launch_bounds__(256) prep_w(
    const float* __restrict__ Wq, const float* __restrict__ Wk,
    const float* __restrict__ Wv, const float* __restrict__ Wf)
{
    const float* src;
    switch (blockIdx.y) {
        case 0: src = Wq; break;
        case 1: src = Wk; break;
        case 2: src = Wv; break;
        default: src = Wf; break;
    }
    const size_t off = (size_t)blockIdx.x * 1024 + threadIdx.x * 4;
    float4 v = *(const float4*)(src + off);
    float4 o = make_float4(rndtf32(v.x), rndtf32(v.y), rndtf32(v.z), rndtf32(v.w));
    *(float4*)(&g_w[blockIdx.y][0] + off) = o;
}

// ---------------------------------------------------------------------------
// tf32 warp-MMA GEMM, cp.async double-buffered staging (no cvt in hot loop).
// Inputs are tf32-exact fp32 (pre-rounded). 128x128 CTA tile, BK=32, 8 warps.
// mode 0: A = g_xr rows (direct), W = g_w[z], out = g_{q,k,v}, round_out=1
// mode 1: A = g_ctx via x-order gather, W = g_w[3], out = out_override
// Dynamic smem: [A0|B0|A1|B1], each 128x36 words = 73,728 B.
// ---------------------------------------------------------------------------
#define LDPAD 36
#define GW    (128 * LDPAD)                 // words per array
#define GEMM_SMEM (4 * GW * 4)              // bytes

__global__ void __launch_bounds__(256) gemm_mma(
    const float* __restrict__ bq, const float* __restrict__ bk,
    const float* __restrict__ bv,
    float* __restrict__ out_override, int mode, int round_out)
{
    extern __shared__ uint32_t dsm[];
    const uint32_t sb = smem_u32(dsm);

    const int tid  = threadIdx.x;
    const int wid  = tid >> 5;
    const int lane = tid & 31;
    const int lr   = lane >> 2;
    const int lc   = lane & 3;
    const int wm0  = (wid >> 2) * 64;
    const int wn0  = (wid & 3) * 32;

    const float* W; const float* bias; float* out; const float* A;
    if (mode == 0) {
        A = g_xr;
        W = &g_w[blockIdx.z][0];
        if (blockIdx.z == 0)      { bias = bq; out = g_q; }
        else if (blockIdx.z == 1) { bias = bk; out = g_k; }
        else                      { bias = bv; out = g_v; }
    } else {
        A = g_ctx; W = &g_w[3][0]; bias = bq; out = out_override;
    }

    const int rm0 = blockIdx.y * 128;
    const int on0 = blockIdx.x * 128;

    const int ldrow = tid >> 3;          // 0..31
    const int ldc4  = (tid & 7) * 4;     // 0..28
    const float* arow[4];
    const float* brow[4];
    uint32_t sts[4];                      // byte offsets within an array
    #pragma unroll
    for (int p = 0; p < 4; p++) {
        int r = rm0 + p * 32 + ldrow;
        int src = r;
        if (mode == 1) {
            int b = r >> 12, s = r & 4095;
            src = ((b << 2) + (s & 3)) * L_ + (s >> 2);
        }
        arow[p] = A + (size_t)src * D_ + ldc4;
        brow[p] = W + (size_t)(on0 + p * 32 + ldrow) * D_ + ldc4;
        sts[p] = (uint32_t)((p * 32 + ldrow) * LDPAD + ldc4) * 4u;
    }

    // prologue: stage chunk 0 into buffer 0
    #pragma unroll
    for (int p = 0; p < 4; p++) {
        cp16(sb + sts[p], arow[p]);
        cp16(sb + GW * 4 + sts[p], brow[p]);
    }
    CP_COMMIT();

    float acc[4][4][4] = {};

    for (int c = 0; c < 32; c++) {
        const int buf = c & 1;
        if (c < 31) {   // stage chunk c+1 into other buffer (overlaps compute)
            const uint32_t ob = (uint32_t)(buf ^ 1) * (2 * GW * 4);
            const int k1 = (c + 1) * 32;
            #pragma unroll
            for (int p = 0; p < 4; p++) {
                cp16(sb + ob + sts[p], arow[p] + k1);
                cp16(sb + ob + GW * 4 + sts[p], brow[p] + k1);
            }
            CP_COMMIT();
            CP_WAIT(1);     // chunk c complete
        } else {
            CP_WAIT(0);
        }
        __syncthreads();

        const uint32_t* As = dsm + buf * 2 * GW;
        const uint32_t* Bs = As + GW;

        #pragma unroll
        for (int kk = 0; kk < 4; kk++) {
            const int kb = kk * 8;
            uint32_t a[4][4], b[4][2];
            #pragma unroll
            for (int mf = 0; mf < 4; mf++) {
                const int r0 = (wm0 + mf * 16 + lr) * LDPAD + kb + lc;
                a[mf][0] = As[r0];
                a[mf][1] = As[r0 + 8 * LDPAD];
                a[mf][2] = As[r0 + 4];
                a[mf][3] = As[r0 + 8 * LDPAD + 4];
            }
            #pragma unroll
            for (int nf = 0; nf < 4; nf++) {
                const int r0 = (wn0 + nf * 8 + lr) * LDPAD + kb + lc;
                b[nf][0] = Bs[r0];
                b[nf][1] = Bs[r0 + 4];
            }
            #pragma unroll
            for (int mf = 0; mf < 4; mf++)
                #pragma unroll
                for (int nf = 0; nf < 4; nf++)
                    mma_tf32(acc[mf][nf], a[mf], b[nf]);
        }
        __syncthreads();   // buf free for reuse at iter c+2
    }

    #pragma unroll
    for (int mf = 0; mf < 4; mf++) {
        const int row0 = rm0 + wm0 + mf * 16 + lr;
        #pragma unroll
        for (int nf = 0; nf < 4; nf++) {
            const int col = on0 + wn0 + nf * 8 + 2 * lc;
            const float bx = bias[col], by = bias[col + 1];
            float o00 = acc[mf][nf][0] + bx, o01 = acc[mf][nf][1] + by;
            float o10 = acc[mf][nf][2] + bx, o11 = acc[mf][nf][3] + by;
            if (round_out) {
                o00 = rndtf32(o00); o01 = rndtf32(o01);
                o10 = rndtf32(o10); o11 = rndtf32(o11);
            }
            *(float2*)(out + (size_t)row0 * D_ + col) = make_float2(o00, o01);
            *(float2*)(out + (size_t)(row0 + 8) * D_ + col) = make_float2(o10, o11);
        }
    }
}

// ---------------------------------------------------------------------------
// Attention via tf32 warp MMA + cp.async double-buffered K/V staging.
// q,k,v are tf32-exact fp32 -> raw copies feed MMA exactly.
// ctx output rounded to tf32 (consumed raw by the out-proj GEMM).
// Dynamic smem: Ks[2] | Vs[2], 69,632 B.
// ---------------------------------------------------------------------------
#define APAD 68
#define KTW  (64 * APAD)

__global__ void __launch_bounds__(128) attn_mma()
{
    extern __shared__ uint32_t dsm[];
    const uint32_t sb = smem_u32(dsm);

    const int tid  = threadIdx.x;
    const int wid  = tid >> 5;
    const int lane = tid & 31;
    const int lr   = lane >> 2;
    const int lc   = lane & 3;
    const int bbh  = blockIdx.y;
    const int bb   = bbh >> 4;
    const int h    = bbh & 15;
    const int q0   = blockIdx.x * 64;

    const int srow = tid >> 1;
    const int scol = (tid & 1) * 32;

    const float* qg = g_q + (size_t)(bb * L_ + q0 + srow) * D_ + h * DH_ + scol;
    const float* kg = g_k + (size_t)(bb * L_) * D_ + h * DH_;
    const float* vg = g_v + (size_t)(bb * L_) * D_ + h * DH_;

    const uint32_t stg = (uint32_t)(srow * APAD + scol) * 4u;

    // group 0: Q -> Ks[1] staging
    #pragma unroll
    for (int j = 0; j < 8; j++)
        cp16(sb + KTW * 4 + stg + j * 16, qg + j * 4);
    CP_COMMIT();
    // group 1: K0,V0 -> buffer 0
    #pragma unroll
    for (int j = 0; j < 8; j++) {
        cp16(sb + stg + j * 16, kg + (size_t)srow * D_ + scol + j * 4);
        cp16(sb + 2 * KTW * 4 + stg + j * 16, vg + (size_t)srow * D_ + scol + j * 4);
    }
    CP_COMMIT();

    CP_WAIT(1);
    __syncthreads();

    uint32_t qa[8][4];
    #pragma unroll
    for (int kk = 0; kk < 8; kk++) {
        const int r0 = KTW + (wid * 16 + lr) * APAD + kk * 8 + lc;
        qa[kk][0] = dsm[r0];
        qa[kk][1] = dsm[r0 + 8 * APAD];
        qa[kk][2] = dsm[r0 + 4];
        qa[kk][3] = dsm[r0 + 8 * APAD + 4];
    }

    float O[8][4] = {};
    float m0 = -1e30f, m1 = -1e30f, l0 = 0.f, l1 = 0.f;

    for (int kt = 0; kt < 16; kt++) {
        const int buf = kt & 1;
        uint32_t* Ks = dsm + buf * KTW;
        uint32_t* Vs = dsm + (2 + buf) * KTW;

        CP_WAIT(0);
        __syncthreads();

        if (kt < 15) {
            const uint32_t ob = (uint32_t)(buf ^ 1) * KTW * 4;
            const float* kp = kg + (size_t)((kt + 1) * 64 + srow) * D_ + scol;
            const float* vp = vg + (size_t)((kt + 1) * 64 + srow) * D_ + scol;
            #pragma unroll
            for (int j = 0; j < 8; j++) {
                cp16(sb + ob + stg + j * 16, kp + j * 4);
                cp16(sb + 2 * KTW * 4 + ob + stg + j * 16, vp + j * 4);
            }
            CP_COMMIT();
        }

        // --- S = Q @ K^T ---
        float s[8][4] = {};
        #pragma unroll
        for (int kk = 0; kk < 8; kk++) {
            uint32_t b[8][2];
            #pragma unroll
            for (int nf = 0; nf < 8; nf++) {
                const int r0 = (nf * 8 + lr) * APAD + kk * 8 + lc;
                b[nf][0] = Ks[r0];
                b[nf][1] = Ks[r0 + 4];
            }
            #pragma unroll
            for (int nf = 0; nf < 8; nf++)
                mma_tf32(s[nf], qa[kk], b[nf]);
        }
        __syncthreads();   // Ks consumed -> reuse as P

        // --- scale + online softmax ---
        float ml0 = -1e30f, ml1 = -1e30f;
        #pragma unroll
        for (int nf = 0; nf < 8; nf++) {
            s[nf][0] *= 0.125f; s[nf][1] *= 0.125f;
            s[nf][2] *= 0.125f; s[nf][3] *= 0.125f;
            ml0 = fmaxf(ml0, fmaxf(s[nf][0], s[nf][1]));
            ml1 = fmaxf(ml1, fmaxf(s[nf][2], s[nf][3]));
        }
        ml0 = fmaxf(ml0, __shfl_xor_sync(0xffffffffu, ml0, 1));
        ml0 = fmaxf(ml0, __shfl_xor_sync(0xffffffffu, ml0, 2));
        ml1 = fmaxf(ml1, __shfl_xor_sync(0xffffffffu, ml1, 1));
        ml1 = fmaxf(ml1, __shfl_xor_sync(0xffffffffu, ml1, 2));
        const float mn0 = fmaxf(m0, ml0), mn1 = fmaxf(m1, ml1);
        const float c0 = __expf(m0 - mn0), c1 = __expf(m1 - mn1);
        float rs0 = 0.f, rs1 = 0.f;
        #pragma unroll
        for (int nf = 0; nf < 8; nf++) {
            s[nf][0] = __expf(s[nf][0] - mn0);
            s[nf][1] = __expf(s[nf][1] - mn0);
            s[nf][2] = __expf(s[nf][2] - mn1);
            s[nf][3] = __expf(s[nf][3] - mn1);
            rs0 += s[nf][0] + s[nf][1];
            rs1 += s[nf][2] + s[nf][3];
        }
        rs0 += __shfl_xor_sync(0xffffffffu, rs0, 1);
        rs0 += __shfl_xor_sync(0xffffffffu, rs0, 2);
        rs1 += __shfl_xor_sync(0xffffffffu, rs1, 1);
        rs1 += __shfl_xor_sync(0xffffffffu, rs1, 2);
        l0 = l0 * c0 + rs0;  m0 = mn0;
        l1 = l1 * c1 + rs1;  m1 = mn1;
        #pragma unroll
        for (int nf = 0; nf < 8; nf++) {
            O[nf][0] *= c0; O[nf][1] *= c0;
            O[nf][2] *= c1; O[nf][3] *= c1;
        }

        // --- P -> SMEM (warp-private rows, rna-rounded) ---
        #pragma unroll
        for (int nf = 0; nf < 8; nf++) {
            const int p0 = (wid * 16 + lr) * APAD + nf * 8 + 2 * lc;
            Ks[p0]                = f2tf32(s[nf][0]);
            Ks[p0 + 1]            = f2tf32(s[nf][1]);
            Ks[p0 + 8 * APAD]     = f2tf32(s[nf][2]);
            Ks[p0 + 8 * APAD + 1] = f2tf32(s[nf][3]);
        }
        __syncwarp();

        // --- O += P @ V ---
        #pragma unroll
        for (int kk = 0; kk < 8; kk++) {
            uint32_t a[4];
            const int r0 = (wid * 16 + lr) * APAD + kk * 8 + lc;
            a[0] = Ks[r0];
            a[1] = Ks[r0 + 8 * APAD];
            a[2] = Ks[r0 + 4];
            a[3] = Ks[r0 + 8 * APAD + 4];
            uint32_t b[8][2];
            #pragma unroll
            for (int nf = 0; nf < 8; nf++) {
                b[nf][0] = Vs[(kk * 8 + lc) * APAD + nf * 8 + lr];
                b[nf][1] = Vs[(kk * 8 + lc + 4) * APAD + nf * 8 + lr];
            }
            #pragma unroll
            for (int nf = 0; nf < 8; nf++)
                mma_tf32(O[nf], a, b[nf]);
        }
        __syncthreads();
    }

    // ctx rounded to tf32: out-proj GEMM consumes it raw.
    const float inv0 = 1.f / l0, inv1 = 1.f / l1;
    float* og = g_ctx + (size_t)(bb * L_ + q0 + wid * 16) * D_ + h * DH_;
    #pragma unroll
    for (int nf = 0; nf < 8; nf++) {
        const int col = nf * 8 + 2 * lc;
        *(float2*)(og + (size_t)lr * D_ + col) =
            make_float2(rndtf32(O[nf][0] * inv0), rndtf32(O[nf][1] * inv0));
        *(float2*)(og + (size_t)(lr + 8) * D_ + col) =
            make_float2(rndtf32(O[nf][2] * inv1), rndtf32(O[nf][3] * inv1));
    }
}

// ---------------------------------------------------------------------------
// final = LayerNorm(atted + x) * gamma + beta.
// ---------------------------------------------------------------------------
__global__ void __launch_bounds__(256) ln_kernel(
    const float* __restrict__ x,
    const float* __restrict__ atted_ext,
    const float* __restrict__ gamma, const float* __restrict__ beta,
    float* __restrict__ final_out)
{
    const float* atted = atted_ext;
    const int r = blockIdx.x;
    const float* xa = x     + (size_t)r * D_;
    const float* aa = atted + (size_t)r * D_;
    const int tid = threadIdx.x;

    float v[4];
    float s1 = 0.f, s2 = 0.f;
    #pragma unroll
    for (int i = 0; i < 4; i++) {
        int c = tid + i * 256;
        float val = xa[c] + aa[c];
        v[i] = val;
        s1 += val; s2 += val * val;
    }
    #pragma unroll
    for (int off = 16; off; off >>= 1) {
        s1 += __shfl_xor_sync(0xffffffffu, s1, off);
        s2 += __shfl_xor_sync(0xffffffffu, s2, off);
    }
    __shared__ float red[16];
    int warp = tid >> 5, lane = tid & 31;
    if (lane == 0) { red[warp] = s1; red[8 + warp] = s2; }
    __syncthreads();
    float t1 = 0.f, t2 = 0.f;
    #pragma unroll
    for (int w = 0; w < 8; w++) { t1 += red[w]; t2 += red[8 + w]; }
    float mu  = t1 * (1.f / 1024.f);
    float var = t2 * (1.f / 1024.f) - mu * mu;
    float rstd = rsqrtf(var + 1e-5f);
    #pragma unroll
    for (int i = 0; i < 4; i++) {
        int c = tid + i * 256;
        final_out[(size_t)r * D_ + c] = (v[i] - mu) * rstd * gamma[c] + beta[c];
    }
}

// ---------------------------------------------------------------------------
extern "C" void kernel_launch(void* const* d_in, const int* in_sizes, int n_in,
                              void* d_out, int out_size)
{
    (void)in_sizes; (void)n_in;
    const float* x     = (const float*)d_in[0];
    const float* Wq    = (const float*)d_in[1];
    const float* bq    = (const float*)d_in[2];
    const float* Wk    = (const float*)d_in[3];
    const float* bk    = (const float*)d_in[4];
    const float* Wv    = (const float*)d_in[5];
    const float* bv    = (const float*)d_in[6];
    const float* Wf    = (const float*)d_in[7];
    const float* bf    = (const float*)d_in[8];
    const float* gamma = (const float*)d_in[9];
    const float* beta  = (const float*)d_in[10];
    float* out = (float*)d_out;

    const long long both = 2LL * R_ * D_;
    float* atted = (out_size >= both) ? (out + (size_t)R_ * D_) : nullptr;
    if (!atted) {
        static float* h_atted_ptr = nullptr;
        if (!h_atted_ptr) cudaGetSymbolAddress((void**)&h_atted_ptr, g_atted);
        atted = h_atted_ptr;
    }

    static bool attr_set = false;
    if (!attr_set) {
        cudaFuncSetAttribute(attn_mma,
                             cudaFuncAttributeMaxDynamicSharedMemorySize,
                             4 * KTW * 4);
        cudaFuncSetAttribute(gemm_mma,
                             cudaFuncAttributeMaxDynamicSharedMemorySize,
                             GEMM_SMEM);
        attr_set = true;
    }

    // Prep: round x (permuted) and weights to tf32-exact fp32.
    prep_x<<<R_ * D_ / 1024, 256>>>(x);
    prep_w<<<dim3(D_ * D_ / 1024, 4), 256>>>(Wq, Wk, Wv, Wf);

    // QKV projections (rounded outputs for attention)
    gemm_mma<<<dim3(D_/128, R_/128, 3), 256, GEMM_SMEM>>>(
        bq, bk, bv, nullptr, 0, 1);
    // Attention (tf32 warp MMA flash, cp.async pipelined; rounded ctx out)
    attn_mma<<<dim3(L_/64, B_ * DIL_ * H_), 128, 4 * KTW * 4>>>();
    // Output projection (fp32 atted out)
    gemm_mma<<<dim3(D_/128, R_/128, 1), 256, GEMM_SMEM>>>(
        bf, nullptr, nullptr, atted, 1, 0);
    ln_kernel<<<R_, 256>>>(x, atted, gamma, beta, out);
}

// round 7
// speedup vs baseline: 1.4572x; 1.3313x over previous
#include <cuda_runtime.h>
#include <cstdint>

// Problem constants
#define B_   2
#define S_   4096
#define D_   1024
#define H_   16
#define DH_  64
#define DIL_ 4
#define L_   1024
#define R_   8192

// Scratch (device globals — no allocation allowed)
__device__ float g_q[(size_t)R_ * D_];
__device__ float g_k[(size_t)R_ * D_];
__device__ float g_v[(size_t)R_ * D_];
__device__ float g_ctx[(size_t)R_ * D_];
__device__ float g_atted[(size_t)R_ * D_];
__device__ float g_xr[(size_t)R_ * D_];        // tf32-rounded, xr-permuted x
__device__ float g_w[4][(size_t)D_ * D_];      // tf32-rounded Wq,Wk,Wv,Wf

// ---------------------------------------------------------------------------
// Helpers
// ---------------------------------------------------------------------------
__device__ __forceinline__ uint32_t f2tf32(float f) {
    uint32_t u;
    asm("cvt.rna.tf32.f32 %0, %1;" : "=r"(u) : "f"(f));
    return u;
}
__device__ __forceinline__ float rndtf32(float f) {
    return __uint_as_float(f2tf32(f));
}

__device__ __forceinline__ void mma_tf32(float c[4], const uint32_t a[4],
                                         const uint32_t b[2]) {
    asm volatile(
        "mma.sync.aligned.m16n8k8.row.col.f32.tf32.tf32.f32 "
        "{%0,%1,%2,%3}, {%4,%5,%6,%7}, {%8,%9}, {%0,%1,%2,%3};"
        : "+f"(c[0]), "+f"(c[1]), "+f"(c[2]), "+f"(c[3])
        : "r"(a[0]), "r"(a[1]), "r"(a[2]), "r"(a[3]), "r"(b[0]), "r"(b[1]));
}

__device__ __forceinline__ uint32_t smem_u32(const void* p) {
    uint32_t a;
    asm("{ .reg .u64 t; cvta.to.shared.u64 t, %1; cvt.u32.u64 %0, t; }"
        : "=r"(a) : "l"(p));
    return a;
}

__device__ __forceinline__ void cp16(uint32_t saddr, const void* gptr) {
    asm volatile("cp.async.ca.shared.global [%0], [%1], 16;"
                 :: "r"(saddr), "l"(gptr));
}
#define CP_COMMIT() asm volatile("cp.async.commit_group;" ::: "memory")
#define CP_WAIT(n)  asm volatile("cp.async.wait_group %0;" :: "n"(n) : "memory")

// ldmatrix x4: four 8x8 b16 tiles == tf32 fragments (lane -> row l>>2, col l&3)
__device__ __forceinline__ void ldm_x4(uint32_t r[4], uint32_t saddr) {
    asm volatile("ldmatrix.sync.aligned.m8n8.x4.shared.b16 {%0,%1,%2,%3}, [%4];"
                 : "=r"(r[0]), "=r"(r[1]), "=r"(r[2]), "=r"(r[3])
                 : "r"(saddr));
}

// ---------------------------------------------------------------------------
// Prep: round + permute x into g_xr; round W's into g_w.
// ---------------------------------------------------------------------------
__global__ void __launch_bounds__(256) prep_x(const float* __restrict__ x)
{
    const int idx = blockIdx.x * 256 + threadIdx.x;
    const int r  = idx >> 8;
    const int c4 = (idx & 255) * 4;
    const int bb = r >> 10, l = r & 1023;
    const int src = ((bb >> 2) << 12) + (l << 2) + (bb & 3);
    float4 v = *(const float4*)(x + (size_t)src * D_ + c4);
    *(float4*)(g_xr + (size_t)r * D_ + c4) =
        make_float4(rndtf32(v.x), rndtf32(v.y), rndtf32(v.z), rndtf32(v.w));
}

__global__ void __launch_bounds__(256) prep_w(
    const float* __restrict__ Wq, const float* __restrict__ Wk,
    const float* __restrict__ Wv, const float* __restrict__ Wf)
{
    const float* src;
    switch (blockIdx.y) {
        case 0: src = Wq; break;
        case 1: src = Wk; break;
        case 2: src = Wv; break;
        default: src = Wf; break;
    }
    const size_t off = (size_t)blockIdx.x * 1024 + threadIdx.x * 4;
    float4 v = *(const float4*)(src + off);
    *(float4*)(&g_w[blockIdx.y][0] + off) =
        make_float4(rndtf32(v.x), rndtf32(v.y), rndtf32(v.z), rndtf32(v.w));
}

// ---------------------------------------------------------------------------
// tf32 warp-MMA GEMM, cp.async double-buffered (unchanged from R5).
// ---------------------------------------------------------------------------
#define LDPAD 36
#define GW    (128 * LDPAD)
#define GEMM_SMEM (4 * GW * 4)

__global__ void __launch_bounds__(256) gemm_mma(
    const float* __restrict__ bq, const float* __restrict__ bk,
    const float* __restrict__ bv,
    float* __restrict__ out_override, int mode, int round_out)
{
    extern __shared__ uint32_t dsm[];
    const uint32_t sb = smem_u32(dsm);

    const int tid  = threadIdx.x;
    const int wid  = tid >> 5;
    const int lane = tid & 31;
    const int lr   = lane >> 2;
    const int lc   = lane & 3;
    const int wm0  = (wid >> 2) * 64;
    const int wn0  = (wid & 3) * 32;

    const float* W; const float* bias; float* out; const float* A;
    if (mode == 0) {
        A = g_xr;
        W = &g_w[blockIdx.z][0];
        if (blockIdx.z == 0)      { bias = bq; out = g_q; }
        else if (blockIdx.z == 1) { bias = bk; out = g_k; }
        else                      { bias = bv; out = g_v; }
    } else {
        A = g_ctx; W = &g_w[3][0]; bias = bq; out = out_override;
    }

    const int rm0 = blockIdx.y * 128;
    const int on0 = blockIdx.x * 128;

    const int ldrow = tid >> 3;
    const int ldc4  = (tid & 7) * 4;
    const float* arow[4];
    const float* brow[4];
    uint32_t sts[4];
    #pragma unroll
    for (int p = 0; p < 4; p++) {
        int r = rm0 + p * 32 + ldrow;
        int src = r;
        if (mode == 1) {
            int b = r >> 12, s = r & 4095;
            src = ((b << 2) + (s & 3)) * L_ + (s >> 2);
        }
        arow[p] = A + (size_t)src * D_ + ldc4;
        brow[p] = W + (size_t)(on0 + p * 32 + ldrow) * D_ + ldc4;
        sts[p] = (uint32_t)((p * 32 + ldrow) * LDPAD + ldc4) * 4u;
    }

    #pragma unroll
    for (int p = 0; p < 4; p++) {
        cp16(sb + sts[p], arow[p]);
        cp16(sb + GW * 4 + sts[p], brow[p]);
    }
    CP_COMMIT();

    float acc[4][4][4] = {};

    for (int c = 0; c < 32; c++) {
        const int buf = c & 1;
        if (c < 31) {
            const uint32_t ob = (uint32_t)(buf ^ 1) * (2 * GW * 4);
            const int k1 = (c + 1) * 32;
            #pragma unroll
            for (int p = 0; p < 4; p++) {
                cp16(sb + ob + sts[p], arow[p] + k1);
                cp16(sb + ob + GW * 4 + sts[p], brow[p] + k1);
            }
            CP_COMMIT();
            CP_WAIT(1);
        } else {
            CP_WAIT(0);
        }
        __syncthreads();

        const uint32_t* As = dsm + buf * 2 * GW;
        const uint32_t* Bs = As + GW;

        #pragma unroll
        for (int kk = 0; kk < 4; kk++) {
            const int kb = kk * 8;
            uint32_t a[4][4], b[4][2];
            #pragma unroll
            for (int mf = 0; mf < 4; mf++) {
                const int r0 = (wm0 + mf * 16 + lr) * LDPAD + kb + lc;
                a[mf][0] = As[r0];
                a[mf][1] = As[r0 + 8 * LDPAD];
                a[mf][2] = As[r0 + 4];
                a[mf][3] = As[r0 + 8 * LDPAD + 4];
            }
            #pragma unroll
            for (int nf = 0; nf < 4; nf++) {
                const int r0 = (wn0 + nf * 8 + lr) * LDPAD + kb + lc;
                b[nf][0] = Bs[r0];
                b[nf][1] = Bs[r0 + 4];
            }
            #pragma unroll
            for (int mf = 0; mf < 4; mf++)
                #pragma unroll
                for (int nf = 0; nf < 4; nf++)
                    mma_tf32(acc[mf][nf], a[mf], b[nf]);
        }
        __syncthreads();
    }

    #pragma unroll
    for (int mf = 0; mf < 4; mf++) {
        const int row0 = rm0 + wm0 + mf * 16 + lr;
        #pragma unroll
        for (int nf = 0; nf < 4; nf++) {
            const int col = on0 + wn0 + nf * 8 + 2 * lc;
            const float bx = bias[col], by = bias[col + 1];
            float o00 = acc[mf][nf][0] + bx, o01 = acc[mf][nf][1] + by;
            float o10 = acc[mf][nf][2] + bx, o11 = acc[mf][nf][3] + by;
            if (round_out) {
                o00 = rndtf32(o00); o01 = rndtf32(o01);
                o10 = rndtf32(o10); o11 = rndtf32(o11);
            }
            *(float2*)(out + (size_t)row0 * D_ + col) = make_float2(o00, o01);
            *(float2*)(out + (size_t)(row0 + 8) * D_ + col) = make_float2(o10, o11);
        }
    }
}

// ---------------------------------------------------------------------------
// Attention: 256 threads (8 warps), q-tile 128, cp.async K/V double buffer,
// ldmatrix.x4 fragment loads, dedicated P buffer (doubles as Q staging).
// smem words: K0|K1|V0|V1 (64*APAD each) then P (128*APAD). 104,448 B.
// ---------------------------------------------------------------------------
#define APAD 68
#define KTW  (64 * APAD)
#define PW   (128 * APAD)
#define ATTN_SMEM ((4 * KTW + PW) * 4)

__global__ void __launch_bounds__(256, 2) attn_mma()
{
    extern __shared__ uint32_t dsm[];
    const uint32_t sb = smem_u32(dsm);

    const int tid  = threadIdx.x;
    const int wid  = tid >> 5;
    const int lane = tid & 31;
    const int lr   = lane >> 2;
    const int lc   = lane & 3;
    const int bbh  = blockIdx.y;
    const int bb   = bbh >> 4;
    const int h    = bbh & 15;
    const int q0   = blockIdx.x * 128;

    // K/V staging pattern: 4 threads per 64-float row
    const int krow = tid >> 2;
    const int kcol = (tid & 3) * 16;
    const uint32_t kstg = (uint32_t)(krow * APAD + kcol) * 4u;

    const float* kg = g_k + (size_t)(bb * L_) * D_ + h * DH_;
    const float* vg = g_v + (size_t)(bb * L_) * D_ + h * DH_;

    // prologue: K0/V0 in flight first
    {
        const float* kp = kg + (size_t)krow * D_ + kcol;
        const float* vp = vg + (size_t)krow * D_ + kcol;
        #pragma unroll
        for (int j = 0; j < 4; j++) {
            cp16(sb + kstg + j * 16, kp + j * 4);
            cp16(sb + 2 * KTW * 4 + kstg + j * 16, vp + j * 4);
        }
        CP_COMMIT();
    }

    // stage Q tile (128x64) into P region while K0/V0 fly
    {
        const int srow = tid >> 1;
        const int scol = (tid & 1) * 32;
        const float* qg = g_q + (size_t)(bb * L_ + q0 + srow) * D_ + h * DH_ + scol;
        float* dst = (float*)(dsm + 4 * KTW) + srow * APAD + scol;
        #pragma unroll
        for (int j = 0; j < 8; j++)
            *(float4*)(dst + j * 4) = *(const float4*)(qg + j * 4);
    }
    __syncthreads();

    // fragment ldmatrix per-lane offsets
    const int aj = lane & 7;
    // A-layout (Q frags & P frags): matrices = [rows, rows+8, rows(+4col), rows+8(+4col)]
    const uint32_t a_off = (uint32_t)((wid * 16 + ((lane >> 3) & 1) * 8 + aj) * APAD
                                      + (lane >> 4) * 4) * 4u;
    // B-layout (K frags): matrices = [nf rows, nf(+4col), nf+1 rows, nf+1(+4col)]
    const uint32_t b_off = (uint32_t)(((lane >> 4) * 8 + aj) * APAD
                                      + ((lane >> 3) & 1) * 4) * 4u;
    const uint32_t pbase = sb + 4 * KTW * 4;

    uint32_t qa[8][4];
    #pragma unroll
    for (int kk = 0; kk < 8; kk++)
        ldm_x4(qa[kk], pbase + a_off + kk * 32);

    float O[8][4] = {};
    float m0 = -1e30f, m1 = -1e30f, l0 = 0.f, l1 = 0.f;

    for (int kt = 0; kt < 16; kt++) {
        const int buf = kt & 1;
        const uint32_t kbuf = sb + (uint32_t)buf * KTW * 4;
        const uint32_t* Vs = dsm + (2 + buf) * KTW;

        CP_WAIT(0);
        __syncthreads();   // tile kt visible; all warps done with buf from kt-2

        if (kt < 15) {     // prefetch kt+1 (safe: after the sync above)
            const uint32_t ob = (uint32_t)(buf ^ 1) * KTW * 4;
            const float* kp = kg + (size_t)((kt + 1) * 64 + krow) * D_ + kcol;
            const float* vp = vg + (size_t)((kt + 1) * 64 + krow) * D_ + kcol;
            #pragma unroll
            for (int j = 0; j < 4; j++) {
                cp16(sb + ob + kstg + j * 16, kp + j * 4);
                cp16(sb + 2 * KTW * 4 + ob + kstg + j * 16, vp + j * 4);
            }
            CP_COMMIT();
        }

        // --- S = Q @ K^T (16x64 per warp), ldmatrix B frags ---
        float s[8][4] = {};
        #pragma unroll
        for (int kk = 0; kk < 8; kk++) {
            #pragma unroll
            for (int p = 0; p < 4; p++) {
                uint32_t bf[4];
                ldm_x4(bf, kbuf + b_off + (uint32_t)(p * 16 * APAD + kk * 8) * 4);
                mma_tf32(s[2 * p],     qa[kk], bf);
                mma_tf32(s[2 * p + 1], qa[kk], bf + 2);
            }
        }

        // --- scale + online softmax (rows lr, lr+8 of this warp) ---
        float ml0 = -1e30f, ml1 = -1e30f;
        #pragma unroll
        for (int nf = 0; nf < 8; nf++) {
            s[nf][0] *= 0.125f; s[nf][1] *= 0.125f;
            s[nf][2] *= 0.125f; s[nf][3] *= 0.125f;
            ml0 = fmaxf(ml0, fmaxf(s[nf][0], s[nf][1]));
            ml1 = fmaxf(ml1, fmaxf(s[nf][2], s[nf][3]));
        }
        ml0 = fmaxf(ml0, __shfl_xor_sync(0xffffffffu, ml0, 1));
        ml0 = fmaxf(ml0, __shfl_xor_sync(0xffffffffu, ml0, 2));
        ml1 = fmaxf(ml1, __shfl_xor_sync(0xffffffffu, ml1, 1));
        ml1 = fmaxf(ml1, __shfl_xor_sync(0xffffffffu, ml1, 2));
        const float mn0 = fmaxf(m0, ml0), mn1 = fmaxf(m1, ml1);
        const float c0 = __expf(m0 - mn0), c1 = __expf(m1 - mn1);
        float rs0 = 0.f, rs1 = 0.f;
        #pragma unroll
        for (int nf = 0; nf < 8; nf++) {
            s[nf][0] = __expf(s[nf][0] - mn0);
            s[nf][1] = __expf(s[nf][1] - mn0);
            s[nf][2] = __expf(s[nf][2] - mn1);
            s[nf][3] = __expf(s[nf][3] - mn1);
            rs0 += s[nf][0] + s[nf][1];
            rs1 += s[nf][2] + s[nf][3];
        }
        rs0 += __shfl_xor_sync(0xffffffffu, rs0, 1);
        rs0 += __shfl_xor_sync(0xffffffffu, rs0, 2);
        rs1 += __shfl_xor_sync(0xffffffffu, rs1, 1);
        rs1 += __shfl_xor_sync(0xffffffffu, rs1, 2);
        l0 = l0 * c0 + rs0;  m0 = mn0;
        l1 = l1 * c1 + rs1;  m1 = mn1;
        #pragma unroll
        for (int nf = 0; nf < 8; nf++) {
            O[nf][0] *= c0; O[nf][1] *= c0;
            O[nf][2] *= c1; O[nf][3] *= c1;
        }

        // --- P -> P buffer (warp-private rows, rna-rounded) ---
        uint32_t* P = dsm + 4 * KTW;
        #pragma unroll
        for (int nf = 0; nf < 8; nf++) {
            const int p0 = (wid * 16 + lr) * APAD + nf * 8 + 2 * lc;
            P[p0]                = f2tf32(s[nf][0]);
            P[p0 + 1]            = f2tf32(s[nf][1]);
            P[p0 + 8 * APAD]     = f2tf32(s[nf][2]);
            P[p0 + 8 * APAD + 1] = f2tf32(s[nf][3]);
        }
        __syncwarp();

        // --- O += P @ V (P frags via ldmatrix) ---
        #pragma unroll
        for (int kk = 0; kk < 8; kk++) {
            uint32_t a[4];
            ldm_x4(a, pbase + a_off + kk * 32);
            uint32_t b[8][2];
            #pragma unroll
            for (int nf = 0; nf < 8; nf++) {
                b[nf][0] = Vs[(kk * 8 + lc) * APAD + nf * 8 + lr];
                b[nf][1] = Vs[(kk * 8 + lc + 4) * APAD + nf * 8 + lr];
            }
            #pragma unroll
            for (int nf = 0; nf < 8; nf++)
                mma_tf32(O[nf], a, b[nf]);
        }
        // no trailing sync: next iteration's top syncthreads covers WAR
    }

    // ctx rounded to tf32 (consumed raw by out-proj GEMM)
    const float inv0 = 1.f / l0, inv1 = 1.f / l1;
    float* og = g_ctx + (size_t)(bb * L_ + q0 + wid * 16) * D_ + h * DH_;
    #pragma unroll
    for (int nf = 0; nf < 8; nf++) {
        const int col = nf * 8 + 2 * lc;
        *(float2*)(og + (size_t)lr * D_ + col) =
            make_float2(rndtf32(O[nf][0] * inv0), rndtf32(O[nf][1] * inv0));
        *(float2*)(og + (size_t)(lr + 8) * D_ + col) =
            make_float2(rndtf32(O[nf][2] * inv1), rndtf32(O[nf][3] * inv1));
    }
}

// ---------------------------------------------------------------------------
// final = LayerNorm(atted + x) * gamma + beta.
// ---------------------------------------------------------------------------
__global__ void __launch_bounds__(256) ln_kernel(
    const float* __restrict__ x,
    const float* __restrict__ atted_ext,
    const float* __restrict__ gamma, const float* __restrict__ beta,
    float* __restrict__ final_out)
{
    const float* atted = atted_ext;
    const int r = blockIdx.x;
    const float* xa = x     + (size_t)r * D_;
    const float* aa = atted + (size_t)r * D_;
    const int tid = threadIdx.x;

    float v[4];
    float s1 = 0.f, s2 = 0.f;
    #pragma unroll
    for (int i = 0; i < 4; i++) {
        int c = tid + i * 256;
        float val = xa[c] + aa[c];
        v[i] = val;
        s1 += val; s2 += val * val;
    }
    #pragma unroll
    for (int off = 16; off; off >>= 1) {
        s1 += __shfl_xor_sync(0xffffffffu, s1, off);
        s2 += __shfl_xor_sync(0xffffffffu, s2, off);
    }
    __shared__ float red[16];
    int warp = tid >> 5, lane = tid & 31;
    if (lane == 0) { red[warp] = s1; red[8 + warp] = s2; }
    __syncthreads();
    float t1 = 0.f, t2 = 0.f;
    #pragma unroll
    for (int w = 0; w < 8; w++) { t1 += red[w]; t2 += red[8 + w]; }
    float mu  = t1 * (1.f / 1024.f);
    float var = t2 * (1.f / 1024.f) - mu * mu;
    float rstd = rsqrtf(var + 1e-5f);
    #pragma unroll
    for (int i = 0; i < 4; i++) {
        int c = tid + i * 256;
        final_out[(size_t)r * D_ + c] = (v[i] - mu) * rstd * gamma[c] + beta[c];
    }
}

// ---------------------------------------------------------------------------
extern "C" void kernel_launch(void* const* d_in, const int* in_sizes, int n_in,
                              void* d_out, int out_size)
{
    (void)in_sizes; (void)n_in;
    const float* x     = (const float*)d_in[0];
    const float* Wq    = (const float*)d_in[1];
    const float* bq    = (const float*)d_in[2];
    const float* Wk    = (const float*)d_in[3];
    const float* bk    = (const float*)d_in[4];
    const float* Wv    = (const float*)d_in[5];
    const float* bv    = (const float*)d_in[6];
    const float* Wf    = (const float*)d_in[7];
    const float* bf    = (const float*)d_in[8];
    const float* gamma = (const float*)d_in[9];
    const float* beta  = (const float*)d_in[10];
    float* out = (float*)d_out;

    const long long both = 2LL * R_ * D_;
    float* atted = (out_size >= both) ? (out + (size_t)R_ * D_) : nullptr;
    if (!atted) {
        static float* h_atted_ptr = nullptr;
        if (!h_atted_ptr) cudaGetSymbolAddress((void**)&h_atted_ptr, g_atted);
        atted = h_atted_ptr;
    }

    static bool attr_set = false;
    if (!attr_set) {
        cudaFuncSetAttribute(attn_mma,
                             cudaFuncAttributeMaxDynamicSharedMemorySize,
                             ATTN_SMEM);
        cudaFuncSetAttribute(gemm_mma,
                             cudaFuncAttributeMaxDynamicSharedMemorySize,
                             GEMM_SMEM);
        attr_set = true;
    }

    prep_x<<<R_ * D_ / 1024, 256>>>(x);
    prep_w<<<dim3(D_ * D_ / 1024, 4), 256>>>(Wq, Wk, Wv, Wf);

    gemm_mma<<<dim3(D_/128, R_/128, 3), 256, GEMM_SMEM>>>(
        bq, bk, bv, nullptr, 0, 1);
    attn_mma<<<dim3(L_/128, B_ * DIL_ * H_), 256, ATTN_SMEM>>>();
    gemm_mma<<<dim3(D_/128, R_/128, 1), 256, GEMM_SMEM>>>(
        bf, nullptr, nullptr, atted, 1, 0);
    ln_kernel<<<R_, 256>>>(x, atted, gamma, beta, out);
}

// round 9
// speedup vs baseline: 2.7364x; 1.8779x over previous
#include <cuda_runtime.h>
#include <cuda_fp16.h>
#include <cstdint>

// Problem constants
#define B_   2
#define S_   4096
#define D_   1024
#define H_   16
#define DH_  64
#define DIL_ 4
#define L_   1024
#define R_   8192

// Scratch (device globals — no allocation allowed)
__device__ __half g_xrh[(size_t)R_ * D_];     // fp16, xr-permuted x
__device__ __half g_wh[4][(size_t)D_ * D_];   // fp16 Wq,Wk,Wv,Wf
__device__ __half g_qh[(size_t)R_ * D_];
__device__ __half g_kh[(size_t)R_ * D_];
__device__ __half g_vh[(size_t)R_ * D_];
__device__ __half g_ctxh[(size_t)R_ * D_];
__device__ float  g_atted[(size_t)R_ * D_];

// ---------------------------------------------------------------------------
// Helpers
// ---------------------------------------------------------------------------
__device__ __forceinline__ void mma_f16(float c[4], const uint32_t a[4],
                                        const uint32_t b0, const uint32_t b1) {
    asm volatile(
        "mma.sync.aligned.m16n8k16.row.col.f32.f16.f16.f32 "
        "{%0,%1,%2,%3}, {%4,%5,%6,%7}, {%8,%9}, {%0,%1,%2,%3};"
        : "+f"(c[0]), "+f"(c[1]), "+f"(c[2]), "+f"(c[3])
        : "r"(a[0]), "r"(a[1]), "r"(a[2]), "r"(a[3]), "r"(b0), "r"(b1));
}

__device__ __forceinline__ uint32_t smem_u32(const void* p) {
    uint32_t a;
    asm("{ .reg .u64 t; cvta.to.shared.u64 t, %1; cvt.u32.u64 %0, t; }"
        : "=r"(a) : "l"(p));
    return a;
}

__device__ __forceinline__ void cp16(uint32_t saddr, const void* gptr) {
    asm volatile("cp.async.ca.shared.global [%0], [%1], 16;"
                 :: "r"(saddr), "l"(gptr));
}
#define CP_COMMIT() asm volatile("cp.async.commit_group;" ::: "memory")
#define CP_WAIT(n)  asm volatile("cp.async.wait_group %0;" :: "n"(n) : "memory")

__device__ __forceinline__ void ldm_x4(uint32_t r[4], uint32_t saddr) {
    asm volatile("ldmatrix.sync.aligned.m8n8.x4.shared.b16 {%0,%1,%2,%3}, [%4];"
                 : "=r"(r[0]), "=r"(r[1]), "=r"(r[2]), "=r"(r[3])
                 : "r"(saddr));
}
__device__ __forceinline__ void ldm_x4t(uint32_t r[4], uint32_t saddr) {
    asm volatile("ldmatrix.sync.aligned.m8n8.x4.trans.shared.b16 {%0,%1,%2,%3}, [%4];"
                 : "=r"(r[0]), "=r"(r[1]), "=r"(r[2]), "=r"(r[3])
                 : "r"(saddr));
}

// ---------------------------------------------------------------------------
// Prep: fp16-round (+permute) x into g_xrh; fp16-round W's into g_wh.
// ---------------------------------------------------------------------------
__global__ void __launch_bounds__(256) prep_x(const float* __restrict__ x)
{
    const int idx = blockIdx.x * 256 + threadIdx.x;
    const int r  = idx >> 8;
    const int c4 = (idx & 255) * 4;
    const int bb = r >> 10, l = r & 1023;
    const int src = ((bb >> 2) << 12) + (l << 2) + (bb & 3);
    float4 v = *(const float4*)(x + (size_t)src * D_ + c4);
    half2 h0 = __floats2half2_rn(v.x, v.y);
    half2 h1 = __floats2half2_rn(v.z, v.w);
    uint2 u = make_uint2(*(uint32_t*)&h0, *(uint32_t*)&h1);
    *(uint2*)(g_xrh + (size_t)r * D_ + c4) = u;
}

__global__ void __launch_bounds__(256) prep_w(
    const float* __restrict__ Wq, const float* __restrict__ Wk,
    const float* __restrict__ Wv, const float* __restrict__ Wf)
{
    const float* src;
    switch (blockIdx.y) {
        case 0: src = Wq; break;
        case 1: src = Wk; break;
        case 2: src = Wv; break;
        default: src = Wf; break;
    }
    const size_t off = (size_t)blockIdx.x * 1024 + threadIdx.x * 4;
    float4 v = *(const float4*)(src + off);
    half2 h0 = __floats2half2_rn(v.x, v.y);
    half2 h1 = __floats2half2_rn(v.z, v.w);
    uint2 u = make_uint2(*(uint32_t*)&h0, *(uint32_t*)&h1);
    *(uint2*)(&g_wh[blockIdx.y][0] + off) = u;
}

// ---------------------------------------------------------------------------
// fp16 warp-MMA GEMM, cp.async double-buffered, ldmatrix fragments.
// C[r,o] = sum_i A[r,i]*W[o,i] + bias[o]; 128x128 tile, BK=32, 8 warps 2x4.
// mode 0: A = g_xrh, W = g_wh[z], out = g_{q,k,v}h (half)
// mode 1: A = g_ctxh (x-order gather), W = g_wh[3], out = fp32 out_f32
// SMEM rows: 32 halves data (64 B) + 16 B pad = 80 B  (16B-aligned rows;
// ldmatrix 16B-chunk index r*5 mod 8 is a permutation -> conflict-free).
// Tile = 128*80 = 10240 B; 4 buffers = 40960 B.
// ---------------------------------------------------------------------------
#define GROWB 80
#define GTILE (128 * GROWB)
#define GEMM_SMEM (4 * GTILE)

__global__ void __launch_bounds__(256) gemm_mma(
    const float* __restrict__ bq, const float* __restrict__ bk,
    const float* __restrict__ bv,
    float* __restrict__ out_f32, int mode)
{
    extern __shared__ char dsmc[];
    const uint32_t sb = smem_u32(dsmc);

    const int tid  = threadIdx.x;
    const int wid  = tid >> 5;
    const int lane = tid & 31;
    const int lr   = lane >> 2;
    const int lc   = lane & 3;
    const int l7   = lane & 7;
    const int lb8  = (lane >> 3) & 1;
    const int lb16 = lane >> 4;
    const int wm0  = (wid >> 2) * 64;
    const int wn0  = (wid & 3) * 32;

    const __half* A; const __half* W; const float* bias;
    __half* outh = nullptr;
    if (mode == 0) {
        A = g_xrh;
        W = &g_wh[blockIdx.z][0];
        if (blockIdx.z == 0)      { bias = bq; outh = g_qh; }
        else if (blockIdx.z == 1) { bias = bk; outh = g_kh; }
        else                      { bias = bv; outh = g_vh; }
    } else {
        A = g_ctxh; W = &g_wh[3][0]; bias = bq;
    }

    const int rm0 = blockIdx.y * 128;
    const int on0 = blockIdx.x * 128;

    // staging: thread t owns row t>>1, 32B segment (t&1)
    const int strow = tid >> 1;
    int srcrow = rm0 + strow;
    if (mode == 1) {
        int b = srcrow >> 12, s = srcrow & 4095;
        srcrow = ((b << 2) + (s & 3)) * L_ + (s >> 2);
    }
    const __half* arow = A + (size_t)srcrow * D_ + (tid & 1) * 16;
    const __half* brow = W + (size_t)(on0 + strow) * D_ + (tid & 1) * 16;
    const uint32_t stso = (uint32_t)(strow * GROWB + (tid & 1) * 32);

    // fragment base offsets (all 16B-aligned)
    const uint32_t aoff = (uint32_t)((wm0 + l7 + lb8 * 8) * GROWB + lb16 * 16);
    const uint32_t boff = (uint32_t)((wn0 + lb16 * 8 + l7) * GROWB + lb8 * 16);

    // prologue: chunk 0 -> buffer 0
    cp16(sb + stso, arow);
    cp16(sb + stso + 16, arow + 8);
    cp16(sb + GTILE + stso, brow);
    cp16(sb + GTILE + stso + 16, brow + 8);
    CP_COMMIT();

    float acc[4][4][4] = {};

    for (int c = 0; c < 32; c++) {
        const int buf = c & 1;
        if (c < 31) {
            const uint32_t ob = (uint32_t)(buf ^ 1) * (2 * GTILE);
            const __half* ga = arow + (c + 1) * 32;
            const __half* gb = brow + (c + 1) * 32;
            cp16(sb + ob + stso, ga);
            cp16(sb + ob + stso + 16, ga + 8);
            cp16(sb + ob + GTILE + stso, gb);
            cp16(sb + ob + GTILE + stso + 16, gb + 8);
            CP_COMMIT();
            CP_WAIT(1);
        } else {
            CP_WAIT(0);
        }
        __syncthreads();

        const uint32_t abuf = sb + (uint32_t)buf * 2 * GTILE;
        const uint32_t bbuf = abuf + GTILE;

        #pragma unroll
        for (int kk = 0; kk < 2; kk++) {
            uint32_t a[4][4], b[2][4];
            #pragma unroll
            for (int mf = 0; mf < 4; mf++)
                ldm_x4(a[mf], abuf + aoff + mf * 16 * GROWB + kk * 32);
            #pragma unroll
            for (int np = 0; np < 2; np++)
                ldm_x4(b[np], bbuf + boff + np * 16 * GROWB + kk * 32);
            #pragma unroll
            for (int mf = 0; mf < 4; mf++) {
                mma_f16(acc[mf][0], a[mf], b[0][0], b[0][1]);
                mma_f16(acc[mf][1], a[mf], b[0][2], b[0][3]);
                mma_f16(acc[mf][2], a[mf], b[1][0], b[1][1]);
                mma_f16(acc[mf][3], a[mf], b[1][2], b[1][3]);
            }
        }
        __syncthreads();
    }

    #pragma unroll
    for (int mf = 0; mf < 4; mf++) {
        const int row0 = rm0 + wm0 + mf * 16 + lr;
        #pragma unroll
        for (int nf = 0; nf < 4; nf++) {
            const int col = on0 + wn0 + nf * 8 + 2 * lc;
            const float bx = bias[col], by = bias[col + 1];
            const float o00 = acc[mf][nf][0] + bx, o01 = acc[mf][nf][1] + by;
            const float o10 = acc[mf][nf][2] + bx, o11 = acc[mf][nf][3] + by;
            if (mode == 0) {
                *(half2*)(outh + (size_t)row0 * D_ + col) =
                    __floats2half2_rn(o00, o01);
                *(half2*)(outh + (size_t)(row0 + 8) * D_ + col) =
                    __floats2half2_rn(o10, o11);
            } else {
                *(float2*)(out_f32 + (size_t)row0 * D_ + col) =
                    make_float2(o00, o01);
                *(float2*)(out_f32 + (size_t)(row0 + 8) * D_ + col) =
                    make_float2(o10, o11);
            }
        }
    }
}

// ---------------------------------------------------------------------------
// fp16 attention: 256 threads (8 warps), q-tile 128, key-tile 64 double-buf.
// K B-frags: plain ldmatrix; V B-frags: ldmatrix.trans (no V transpose copy).
// SMEM rows 64 halves (128 B) + 16 B pad = 144 B (aligned, conflict-free).
// K0|K1|V0|V1 (9216 B each) + P/Q (18432 B) = 55296 B -> 2 CTAs/SM.
// ---------------------------------------------------------------------------
#define AROWB 144
#define KTB   (64 * AROWB)
#define PTB   (128 * AROWB)
#define PBASE (4 * KTB)
#define ATTN_SMEM (4 * KTB + PTB)

__global__ void __launch_bounds__(256, 2) attn_mma()
{
    extern __shared__ char dsmc[];
    const uint32_t sb = smem_u32(dsmc);

    const int tid  = threadIdx.x;
    const int wid  = tid >> 5;
    const int lane = tid & 31;
    const int lr   = lane >> 2;
    const int lc   = lane & 3;
    const int l7   = lane & 7;
    const int lb8  = (lane >> 3) & 1;
    const int lb16 = lane >> 4;
    const int bbh  = blockIdx.y;
    const int bb   = bbh >> 4;
    const int h    = bbh & 15;
    const int q0   = blockIdx.x * 128;

    // K/V staging: thread t -> row t>>2 (0..63), 32B seg (t&3)
    const int krow = tid >> 2;
    const int kseg = tid & 3;
    const uint32_t kstg = (uint32_t)(krow * AROWB + kseg * 32);

    const __half* kg = g_kh + (size_t)(bb * L_) * D_ + h * DH_;
    const __half* vg = g_vh + (size_t)(bb * L_) * D_ + h * DH_;

    // prologue: K0/V0 in flight
    {
        const __half* kp = kg + (size_t)krow * D_ + kseg * 16;
        const __half* vp = vg + (size_t)krow * D_ + kseg * 16;
        cp16(sb + kstg, kp);
        cp16(sb + kstg + 16, kp + 8);
        cp16(sb + 2 * KTB + kstg, vp);
        cp16(sb + 2 * KTB + kstg + 16, vp + 8);
        CP_COMMIT();
    }

    // stage Q (128 x 64 halves) into P region while K0/V0 fly
    {
        const int srow = tid >> 1;
        const __half* qg = g_qh + (size_t)(bb * L_ + q0 + srow) * D_ + h * DH_
                           + (tid & 1) * 32;
        char* dst = dsmc + PBASE + srow * AROWB + (tid & 1) * 64;
        #pragma unroll
        for (int j = 0; j < 4; j++)
            *(uint4*)(dst + j * 16) = *(const uint4*)(qg + j * 8);
    }
    __syncthreads();

    // fragment offsets
    const int q_row = wid * 16 + l7 + lb8 * 8;
    const uint32_t qoff = sb + PBASE + (uint32_t)(q_row * AROWB + lb16 * 16);
    const uint32_t koff = (uint32_t)((lb16 * 8 + l7) * AROWB + lb8 * 16);
    const uint32_t voff = (uint32_t)((l7 + lb8 * 8) * AROWB + lb16 * 16);

    uint32_t qa[4][4];
    #pragma unroll
    for (int kk = 0; kk < 4; kk++)
        ldm_x4(qa[kk], qoff + kk * 32);

    float O[8][4] = {};
    float m0 = -1e30f, m1 = -1e30f, l0 = 0.f, l1 = 0.f;

    for (int kt = 0; kt < 16; kt++) {
        const int buf = kt & 1;
        const uint32_t kbuf = sb + (uint32_t)buf * KTB;
        const uint32_t vbuf = sb + (uint32_t)(2 + buf) * KTB;

        CP_WAIT(0);
        __syncthreads();

        if (kt < 15) {
            const uint32_t ob = (uint32_t)(buf ^ 1) * KTB;
            const __half* kp = kg + (size_t)((kt + 1) * 64 + krow) * D_ + kseg * 16;
            const __half* vp = vg + (size_t)((kt + 1) * 64 + krow) * D_ + kseg * 16;
            cp16(sb + ob + kstg, kp);
            cp16(sb + ob + kstg + 16, kp + 8);
            cp16(sb + 2 * KTB + ob + kstg, vp);
            cp16(sb + 2 * KTB + ob + kstg + 16, vp + 8);
            CP_COMMIT();
        }

        // --- S = Q @ K^T (16 x 64 per warp): 16 ldm + 32 MMA ---
        float s[8][4] = {};
        #pragma unroll
        for (int kk = 0; kk < 4; kk++) {
            #pragma unroll
            for (int np = 0; np < 4; np++) {
                uint32_t b[4];
                ldm_x4(b, kbuf + koff + (uint32_t)(np * 16 * AROWB + kk * 32));
                mma_f16(s[2 * np],     qa[kk], b[0], b[1]);
                mma_f16(s[2 * np + 1], qa[kk], b[2], b[3]);
            }
        }

        // --- scale + online softmax (rows lr, lr+8) ---
        float ml0 = -1e30f, ml1 = -1e30f;
        #pragma unroll
        for (int nf = 0; nf < 8; nf++) {
            s[nf][0] *= 0.125f; s[nf][1] *= 0.125f;
            s[nf][2] *= 0.125f; s[nf][3] *= 0.125f;
            ml0 = fmaxf(ml0, fmaxf(s[nf][0], s[nf][1]));
            ml1 = fmaxf(ml1, fmaxf(s[nf][2], s[nf][3]));
        }
        ml0 = fmaxf(ml0, __shfl_xor_sync(0xffffffffu, ml0, 1));
        ml0 = fmaxf(ml0, __shfl_xor_sync(0xffffffffu, ml0, 2));
        ml1 = fmaxf(ml1, __shfl_xor_sync(0xffffffffu, ml1, 1));
        ml1 = fmaxf(ml1, __shfl_xor_sync(0xffffffffu, ml1, 2));
        const float mn0 = fmaxf(m0, ml0), mn1 = fmaxf(m1, ml1);
        const float c0 = __expf(m0 - mn0), c1 = __expf(m1 - mn1);
        float rs0 = 0.f, rs1 = 0.f;
        #pragma unroll
        for (int nf = 0; nf < 8; nf++) {
            s[nf][0] = __expf(s[nf][0] - mn0);
            s[nf][1] = __expf(s[nf][1] - mn0);
            s[nf][2] = __expf(s[nf][2] - mn1);
            s[nf][3] = __expf(s[nf][3] - mn1);
            rs0 += s[nf][0] + s[nf][1];
            rs1 += s[nf][2] + s[nf][3];
        }
        rs0 += __shfl_xor_sync(0xffffffffu, rs0, 1);
        rs0 += __shfl_xor_sync(0xffffffffu, rs0, 2);
        rs1 += __shfl_xor_sync(0xffffffffu, rs1, 1);
        rs1 += __shfl_xor_sync(0xffffffffu, rs1, 2);
        l0 = l0 * c0 + rs0;  m0 = mn0;
        l1 = l1 * c1 + rs1;  m1 = mn1;
        #pragma unroll
        for (int nf = 0; nf < 8; nf++) {
            O[nf][0] *= c0; O[nf][1] *= c0;
            O[nf][2] *= c1; O[nf][3] *= c1;
        }

        // --- P -> P buffer as half2 (conflict-free STS.32) ---
        {
            char* P0 = dsmc + PBASE + (wid * 16 + lr) * AROWB + 4 * lc;
            char* P1 = P0 + 8 * AROWB;
            #pragma unroll
            for (int nf = 0; nf < 8; nf++) {
                *(half2*)(P0 + nf * 16) = __floats2half2_rn(s[nf][0], s[nf][1]);
                *(half2*)(P1 + nf * 16) = __floats2half2_rn(s[nf][2], s[nf][3]);
            }
        }
        __syncwarp();

        // --- O += P @ V: P frags plain ldm, V frags ldm.trans ---
        #pragma unroll
        for (int kk = 0; kk < 4; kk++) {
            uint32_t a[4];
            ldm_x4(a, qoff + kk * 32);
            #pragma unroll
            for (int np = 0; np < 4; np++) {
                uint32_t b[4];
                ldm_x4t(b, vbuf + voff + (uint32_t)(kk * 16 * AROWB + np * 32));
                mma_f16(O[2 * np],     a, b[0], b[1]);
                mma_f16(O[2 * np + 1], a, b[2], b[3]);
            }
        }
        // next iteration's top __syncthreads covers the WAR on P/K/V
    }

    // ctx (half) out
    const float inv0 = 1.f / l0, inv1 = 1.f / l1;
    __half* og = g_ctxh + (size_t)(bb * L_ + q0 + wid * 16) * D_ + h * DH_;
    #pragma unroll
    for (int nf = 0; nf < 8; nf++) {
        const int col = nf * 8 + 2 * lc;
        *(half2*)(og + (size_t)lr * D_ + col) =
            __floats2half2_rn(O[nf][0] * inv0, O[nf][1] * inv0);
        *(half2*)(og + (size_t)(lr + 8) * D_ + col) =
            __floats2half2_rn(O[nf][2] * inv1, O[nf][3] * inv1);
    }
}

// ---------------------------------------------------------------------------
// final = LayerNorm(atted + x) * gamma + beta.
// ---------------------------------------------------------------------------
__global__ void __launch_bounds__(256) ln_kernel(
    const float* __restrict__ x,
    const float* __restrict__ atted_ext,
    const float* __restrict__ gamma, const float* __restrict__ beta,
    float* __restrict__ final_out)
{
    const float* atted = atted_ext;
    const int r = blockIdx.x;
    const float* xa = x     + (size_t)r * D_;
    const float* aa = atted + (size_t)r * D_;
    const int tid = threadIdx.x;

    float v[4];
    float s1 = 0.f, s2 = 0.f;
    #pragma unroll
    for (int i = 0; i < 4; i++) {
        int c = tid + i * 256;
        float val = xa[c] + aa[c];
        v[i] = val;
        s1 += val; s2 += val * val;
    }
    #pragma unroll
    for (int off = 16; off; off >>= 1) {
        s1 += __shfl_xor_sync(0xffffffffu, s1, off);
        s2 += __shfl_xor_sync(0xffffffffu, s2, off);
    }
    __shared__ float red[16];
    int warp = tid >> 5, lane = tid & 31;
    if (lane == 0) { red[warp] = s1; red[8 + warp] = s2; }
    __syncthreads();
    float t1 = 0.f, t2 = 0.f;
    #pragma unroll
    for (int w = 0; w < 8; w++) { t1 += red[w]; t2 += red[8 + w]; }
    float mu  = t1 * (1.f / 1024.f);
    float var = t2 * (1.f / 1024.f) - mu * mu;
    float rstd = rsqrtf(var + 1e-5f);
    #pragma unroll
    for (int i = 0; i < 4; i++) {
        int c = tid + i * 256;
        final_out[(size_t)r * D_ + c] = (v[i] - mu) * rstd * gamma[c] + beta[c];
    }
}

// ---------------------------------------------------------------------------
extern "C" void kernel_launch(void* const* d_in, const int* in_sizes, int n_in,
                              void* d_out, int out_size)
{
    (void)in_sizes; (void)n_in;
    const float* x     = (const float*)d_in[0];
    const float* Wq    = (const float*)d_in[1];
    const float* bq    = (const float*)d_in[2];
    const float* Wk    = (const float*)d_in[3];
    const float* bk    = (const float*)d_in[4];
    const float* Wv    = (const float*)d_in[5];
    const float* bv    = (const float*)d_in[6];
    const float* Wf    = (const float*)d_in[7];
    const float* bf    = (const float*)d_in[8];
    const float* gamma = (const float*)d_in[9];
    const float* beta  = (const float*)d_in[10];
    float* out = (float*)d_out;

    const long long both = 2LL * R_ * D_;
    float* atted = (out_size >= both) ? (out + (size_t)R_ * D_) : nullptr;
    if (!atted) {
        static float* h_atted_ptr = nullptr;
        if (!h_atted_ptr) cudaGetSymbolAddress((void**)&h_atted_ptr, g_atted);
        atted = h_atted_ptr;
    }

    static bool attr_set = false;
    if (!attr_set) {
        cudaFuncSetAttribute(attn_mma,
                             cudaFuncAttributeMaxDynamicSharedMemorySize,
                             ATTN_SMEM);
        cudaFuncSetAttribute(gemm_mma,
                             cudaFuncAttributeMaxDynamicSharedMemorySize,
                             GEMM_SMEM);
        attr_set = true;
    }

    prep_x<<<R_ * D_ / 1024, 256>>>(x);
    prep_w<<<dim3(D_ * D_ / 1024, 4), 256>>>(Wq, Wk, Wv, Wf);

    gemm_mma<<<dim3(D_/128, R_/128, 3), 256, GEMM_SMEM>>>(
        bq, bk, bv, nullptr, 0);
    attn_mma<<<dim3(L_/128, B_ * DIL_ * H_), 256, ATTN_SMEM>>>();
    gemm_mma<<<dim3(D_/128, R_/128, 1), 256, GEMM_SMEM>>>(
        bf, nullptr, nullptr, atted, 1);
    ln_kernel<<<R_, 256>>>(x, atted, gamma, beta, out);
}